// round 13
// baseline (speedup 1.0000x reference)
#include <cuda_runtime.h>
#include <cuda_bf16.h>
#include <cstdint>

#define NEXP  8
#define TOPK  2
#define NTOK  4096
#define HID   1024
#define INTER 3584
#define KC    32

// ---------------------------------------------------------------------------
// Device scratch (zero-initialized globals)
// ---------------------------------------------------------------------------
__device__ int   g_count[NEXP];
__device__ int   g_tok[NEXP * NTOK];
__device__ float g_gate[NEXP * NTOK];

// pre-split operands (hi/lo bf16). Weights stored TRANSPOSED: [e][n][k], k-contig
__device__ __nv_bfloat16 g_xh[(size_t)NTOK * HID];
__device__ __nv_bfloat16 g_xl[(size_t)NTOK * HID];
__device__ __nv_bfloat16 g_w1h[(size_t)NEXP * INTER * HID];
__device__ __nv_bfloat16 g_w1l[(size_t)NEXP * INTER * HID];
__device__ __nv_bfloat16 g_w3h[(size_t)NEXP * INTER * HID];
__device__ __nv_bfloat16 g_w3l[(size_t)NEXP * INTER * HID];
__device__ __nv_bfloat16 g_w2h[(size_t)NEXP * HID * INTER];
__device__ __nv_bfloat16 g_w2l[(size_t)NEXP * HID * INTER];
// H intermediate, pre-split; rows >= cnt stay zero forever
__device__ __nv_bfloat16 g_hh[(size_t)NEXP * NTOK * INTER];
__device__ __nv_bfloat16 g_hl[(size_t)NEXP * NTOK * INTER];

// ---------------------------------------------------------------------------
// Helpers
// ---------------------------------------------------------------------------
__device__ __forceinline__ uint32_t smem_u32(const void* p) {
    uint32_t a;
    asm("{ .reg .u64 t; cvta.to.shared.u64 t, %1; cvt.u32.u64 %0, t; }"
        : "=r"(a) : "l"(p));
    return a;
}
__device__ __forceinline__ void cp16(uint32_t dst, const void* src) {
    asm volatile("cp.async.cg.shared.global [%0], [%1], 16;\n" :: "r"(dst), "l"(src));
}
__device__ __forceinline__ void cp_commit() {
    asm volatile("cp.async.commit_group;\n");
}
template <int N> __device__ __forceinline__ void cp_wait() {
    asm volatile("cp.async.wait_group %0;\n" :: "n"(N));
}
__device__ __forceinline__ void split2(float x, float y, uint32_t& h, uint32_t& l) {
    __nv_bfloat16 xh = __float2bfloat16(x);
    __nv_bfloat16 yh = __float2bfloat16(y);
    float xr = x - __bfloat162float(xh);
    float yr = y - __bfloat162float(yh);
    __nv_bfloat162 hh; hh.x = xh; hh.y = yh;
    __nv_bfloat162 ll = __floats2bfloat162_rn(xr, yr);
    h = *reinterpret_cast<uint32_t*>(&hh);
    l = *reinterpret_cast<uint32_t*>(&ll);
}
// b0 = (n-group, k0-7), b1 = (n-group, k8-15) — may be NON-contiguous registers
__device__ __forceinline__ void mma_bf16(float d[4], const uint32_t a[4],
                                         uint32_t b0, uint32_t b1) {
    asm volatile(
        "mma.sync.aligned.m16n8k16.row.col.f32.bf16.bf16.f32 "
        "{%0,%1,%2,%3}, {%4,%5,%6,%7}, {%8,%9}, {%0,%1,%2,%3};"
        : "+f"(d[0]), "+f"(d[1]), "+f"(d[2]), "+f"(d[3])
        : "r"(a[0]), "r"(a[1]), "r"(a[2]), "r"(a[3]), "r"(b0), "r"(b1));
}
__device__ __forceinline__ void ldsm4(uint32_t r[4], uint32_t addr) {
    asm volatile("ldmatrix.sync.aligned.m8n8.x4.shared.b16 {%0,%1,%2,%3}, [%4];"
                 : "=r"(r[0]), "=r"(r[1]), "=r"(r[2]), "=r"(r[3]) : "r"(addr));
}

// swizzled byte offset of 16B chunk c in 64B row r
#define SWC(r, c) ((((c) ^ (((r) >> 1) & 3))) * 16)

// ---------------------------------------------------------------------------
// Routing
// ---------------------------------------------------------------------------
__global__ void zero_counts_kernel() {
    if (threadIdx.x < NEXP) g_count[threadIdx.x] = 0;
}
__global__ void route_kernel(const int* __restrict__ mask,
                             const float* __restrict__ rw) {
    int idx = blockIdx.x * blockDim.x + threadIdx.x;
    if (idx >= NTOK * TOPK) return;
    int t = idx >> 1, k = idx & 1;
#pragma unroll
    for (int e = 0; e < NEXP; e++) {
        if (mask[(e * TOPK + k) * NTOK + t] != 0) {
            int slot = atomicAdd(&g_count[e], 1);
            g_tok[e * NTOK + slot]  = t;
            g_gate[e * NTOK + slot] = rw[t * TOPK + k];
            return;
        }
    }
}

// ---------------------------------------------------------------------------
// Pre-pass: split X (already k-contiguous)
// ---------------------------------------------------------------------------
__global__ void split_x_kernel(const float* __restrict__ x) {
    size_t i = ((size_t)blockIdx.x * blockDim.x + threadIdx.x) * 2;
    float2 v = *(const float2*)(x + i);
    uint32_t h, l;
    split2(v.x, v.y, h, l);
    *(uint32_t*)&g_xh[i] = h;
    *(uint32_t*)&g_xl[i] = l;
}

// ---------------------------------------------------------------------------
// Pre-pass: transpose + split weights. src [e][K][N] fp32 -> dst [e][N][K] bf16
// ---------------------------------------------------------------------------
template <int W>
__global__ void transpose_split_kernel(const float* __restrict__ src, int K, int N) {
    __shared__ float tile[32][33];
    const int e  = blockIdx.z;
    const int n0 = blockIdx.x * 32, k0 = blockIdx.y * 32;
    const int tx = threadIdx.x, ty = threadIdx.y;
    const float* s = src + ((size_t)e * K + k0) * N + n0;
#pragma unroll
    for (int j = 0; j < 4; j++)
        tile[ty + j * 8][tx] = s[(size_t)(ty + j * 8) * N + tx];
    __syncthreads();
    __nv_bfloat16* dh = (W == 0) ? g_w1h : (W == 1) ? g_w3h : g_w2h;
    __nv_bfloat16* dl = (W == 0) ? g_w1l : (W == 1) ? g_w3l : g_w2l;
    const int tid = ty * 32 + tx;
    const int kp  = tid & 15;
    const int nb  = tid >> 4;
#pragma unroll
    for (int it = 0; it < 2; it++) {
        int nl = nb + it * 16;
        uint32_t h, l;
        split2(tile[kp * 2][nl], tile[kp * 2 + 1][nl], h, l);
        size_t o = ((size_t)e * N + n0 + nl) * K + k0;
        ((uint32_t*)(dh + o))[kp] = h;
        ((uint32_t*)(dl + o))[kp] = l;
    }
}

// ---------------------------------------------------------------------------
// SMEM layouts: 64B rows, XOR-swizzled, 3-stage ring
// ---------------------------------------------------------------------------
#define S1_AH  0
#define S1_AL  8192
#define S1_B1H 16384
#define S1_B1L 24576
#define S1_B3H 32768
#define S1_B3L 40960
#define S1_STG 49152
#define SMEM1  (3 * S1_STG)    // 147456

#define S2_AH  0
#define S2_AL  8192
#define S2_BH  16384
#define S2_BL  24576
#define S2_STG 32768
#define SMEM2  (3 * S2_STG)    // 98304

// ---------------------------------------------------------------------------
// GEMM1: D1 = Xg@W1, D3 = Xg@W3, H = silu(D1)*D3 (split) -> g_hh/g_hl
// CTA 128x128, 8 warps (2m x 4n), warp 64x32 per matrix.
// 3-stage cp.async ring, ONE barrier per chunk.
// ---------------------------------------------------------------------------
__global__ __launch_bounds__(256, 1)
void gemm1_kernel() {
    const int e   = blockIdx.z;
    const int cnt = g_count[e];
    const int m0  = blockIdx.y * 128;
    if (m0 >= cnt) return;
    const int n0  = blockIdx.x * 128;

    extern __shared__ char smem[];
    const uint32_t sb = smem_u32(smem);
    const int tid = threadIdx.x, lane = tid & 31, wid = tid >> 5;
    const int wm = wid & 1, wn = wid >> 1;

    const int srow = tid >> 1;
    const int sc0  = (tid & 1) * 2;
    int grow = m0 + srow; if (grow >= cnt) grow = cnt - 1;
    const size_t xoff = (size_t)g_tok[e * NTOK + grow] * HID + sc0 * 8;
    const size_t boff = ((size_t)(e * INTER + n0 + srow)) * HID + sc0 * 8;
    const uint32_t d0 = (uint32_t)(srow * 64 + SWC(srow, sc0));
    const uint32_t d1 = (uint32_t)(srow * 64 + SWC(srow, sc0 + 1));

    auto issue = [&](int c) {
        const uint32_t so = sb + (uint32_t)((c % 3) * S1_STG);
        const size_t ko = (size_t)c * KC;
        cp16(so + S1_AH  + d0, g_xh  + xoff + ko);
        cp16(so + S1_AH  + d1, g_xh  + xoff + ko + 8);
        cp16(so + S1_AL  + d0, g_xl  + xoff + ko);
        cp16(so + S1_AL  + d1, g_xl  + xoff + ko + 8);
        cp16(so + S1_B1H + d0, g_w1h + boff + ko);
        cp16(so + S1_B1H + d1, g_w1h + boff + ko + 8);
        cp16(so + S1_B1L + d0, g_w1l + boff + ko);
        cp16(so + S1_B1L + d1, g_w1l + boff + ko + 8);
        cp16(so + S1_B3H + d0, g_w3h + boff + ko);
        cp16(so + S1_B3H + d1, g_w3h + boff + ko + 8);
        cp16(so + S1_B3L + d0, g_w3l + boff + ko);
        cp16(so + S1_B3L + d1, g_w3l + boff + ko + 8);
        cp_commit();
    };

    const int rA = lane & 15, cA = lane >> 4, mA = (rA >> 1) & 3;
    const uint32_t aRow = (uint32_t)((wm * 64 + rA) * 64);
    const uint32_t swA0 = (uint32_t)(((cA) ^ mA) * 16);
    const uint32_t swA1 = (uint32_t)(((2 + cA) ^ mA) * 16);
    // B via x4: lanes 0-7 -> (rows 0-7, k0-7), 8-15 -> (rows 8-15, k0-7),
    //           16-23 -> (rows 0-7, k8-15), 24-31 -> (rows 8-15, k8-15)
    const int rB = lane & 15, cB = lane >> 4, mB = (rB >> 1) & 3;
    const uint32_t bRow = (uint32_t)((wn * 32 + rB) * 64);
    const uint32_t swB0 = (uint32_t)(((cB) ^ mB) * 16);
    const uint32_t swB1 = (uint32_t)(((2 + cB) ^ mB) * 16);

    float acc1[4][4][4] = {};
    float acc3[4][4][4] = {};

    issue(0);
    issue(1);
    const int NC = HID / KC;   // 32
    for (int c = 0; c < NC; c++) {
        cp_wait<1>();
        __syncthreads();           // all warps done reading chunk c-1
        if (c + 2 < NC) issue(c + 2);
        const uint32_t s = sb + (uint32_t)((c % 3) * S1_STG);
#pragma unroll
        for (int ks = 0; ks < 2; ks++) {
            const uint32_t swa = ks ? swA1 : swA0;
            const uint32_t swb = ks ? swB1 : swB0;
            uint32_t ah[4][4], al[4][4];
#pragma unroll
            for (int mi = 0; mi < 4; mi++) {
                ldsm4(ah[mi], s + S1_AH + aRow + mi * 1024 + swa);
                ldsm4(al[mi], s + S1_AL + aRow + mi * 1024 + swa);
            }
#pragma unroll
            for (int np = 0; np < 2; np++) {      // 16 n-rows per np
                const uint32_t bo = bRow + np * 1024 + swb;
                uint32_t bh[4], bl[4];
                ldsm4(bh, s + S1_B1H + bo);
                ldsm4(bl, s + S1_B1L + bo);
#pragma unroll
                for (int q = 0; q < 2; q++) {
                    const int ni = 2 * np + q;
                    // pair {k0-7, k8-15} of n-group q: regs q and q+2
#pragma unroll
                    for (int mi = 0; mi < 4; mi++) {
                        mma_bf16(acc1[mi][ni], ah[mi], bh[q], bh[q + 2]);
                        mma_bf16(acc1[mi][ni], al[mi], bh[q], bh[q + 2]);
                        mma_bf16(acc1[mi][ni], ah[mi], bl[q], bl[q + 2]);
                    }
                }
                ldsm4(bh, s + S1_B3H + bo);
                ldsm4(bl, s + S1_B3L + bo);
#pragma unroll
                for (int q = 0; q < 2; q++) {
                    const int ni = 2 * np + q;
#pragma unroll
                    for (int mi = 0; mi < 4; mi++) {
                        mma_bf16(acc3[mi][ni], ah[mi], bh[q], bh[q + 2]);
                        mma_bf16(acc3[mi][ni], al[mi], bh[q], bh[q + 2]);
                        mma_bf16(acc3[mi][ni], ah[mi], bl[q], bl[q + 2]);
                    }
                }
            }
        }
    }

    // epilogue: silu(D1)*D3, split, store
    const int g = lane >> 2, tig = lane & 3;
#pragma unroll
    for (int mi = 0; mi < 4; mi++)
#pragma unroll
    for (int half = 0; half < 2; half++) {
        const int r = m0 + wm * 64 + mi * 16 + g + half * 8;
        if (r < cnt) {
            const size_t base = ((size_t)e * NTOK + r) * INTER + n0 + wn * 32 + tig * 2;
#pragma unroll
            for (int ni = 0; ni < 4; ni++) {
                float x0 = acc1[mi][ni][half * 2 + 0];
                float x1 = acc1[mi][ni][half * 2 + 1];
                float h0 = (x0 / (1.f + __expf(-x0))) * acc3[mi][ni][half * 2 + 0];
                float h1 = (x1 / (1.f + __expf(-x1))) * acc3[mi][ni][half * 2 + 1];
                uint32_t hh, ll;
                split2(h0, h1, hh, ll);
                *(uint32_t*)&g_hh[base + ni * 8] = hh;
                *(uint32_t*)&g_hl[base + ni * 8] = ll;
            }
        }
    }
}

// ---------------------------------------------------------------------------
// GEMM2: out += gate * (H_e @ W2_e)
// ---------------------------------------------------------------------------
__global__ __launch_bounds__(256, 2)
void gemm2_kernel(float* __restrict__ out) {
    const int e   = blockIdx.z;
    const int cnt = g_count[e];
    const int m0  = blockIdx.y * 128;
    if (m0 >= cnt) return;
    const int n0  = blockIdx.x * 128;

    extern __shared__ char smem[];
    const uint32_t sb = smem_u32(smem);
    const int tid = threadIdx.x, lane = tid & 31, wid = tid >> 5;
    const int wm = wid & 1, wn = wid >> 1;

    const int srow = tid >> 1;
    const int sc0  = (tid & 1) * 2;
    const size_t aoff = ((size_t)e * NTOK + m0 + srow) * INTER + sc0 * 8;
    const size_t boff = ((size_t)(e * HID + n0 + srow)) * INTER + sc0 * 8;
    const uint32_t d0 = (uint32_t)(srow * 64 + SWC(srow, sc0));
    const uint32_t d1 = (uint32_t)(srow * 64 + SWC(srow, sc0 + 1));

    auto issue = [&](int c) {
        const uint32_t so = sb + (uint32_t)((c % 3) * S2_STG);
        const size_t ko = (size_t)c * KC;
        cp16(so + S2_AH + d0, g_hh  + aoff + ko);
        cp16(so + S2_AH + d1, g_hh  + aoff + ko + 8);
        cp16(so + S2_AL + d0, g_hl  + aoff + ko);
        cp16(so + S2_AL + d1, g_hl  + aoff + ko + 8);
        cp16(so + S2_BH + d0, g_w2h + boff + ko);
        cp16(so + S2_BH + d1, g_w2h + boff + ko + 8);
        cp16(so + S2_BL + d0, g_w2l + boff + ko);
        cp16(so + S2_BL + d1, g_w2l + boff + ko + 8);
        cp_commit();
    };

    const int rA = lane & 15, cA = lane >> 4, mA = (rA >> 1) & 3;
    const uint32_t aRow = (uint32_t)((wm * 64 + rA) * 64);
    const uint32_t swA0 = (uint32_t)(((cA) ^ mA) * 16);
    const uint32_t swA1 = (uint32_t)(((2 + cA) ^ mA) * 16);
    const int rB = lane & 15, cB = lane >> 4, mB = (rB >> 1) & 3;
    const uint32_t bRow = (uint32_t)((wn * 32 + rB) * 64);
    const uint32_t swB0 = (uint32_t)(((cB) ^ mB) * 16);
    const uint32_t swB1 = (uint32_t)(((2 + cB) ^ mB) * 16);

    float acc[4][4][4] = {};

    issue(0);
    issue(1);
    const int NC = INTER / KC;   // 112
    for (int c = 0; c < NC; c++) {
        cp_wait<1>();
        __syncthreads();
        if (c + 2 < NC) issue(c + 2);
        const uint32_t s = sb + (uint32_t)((c % 3) * S2_STG);
#pragma unroll
        for (int ks = 0; ks < 2; ks++) {
            const uint32_t swa = ks ? swA1 : swA0;
            const uint32_t swb = ks ? swB1 : swB0;
            uint32_t ah[4][4], al[4][4];
#pragma unroll
            for (int mi = 0; mi < 4; mi++) {
                ldsm4(ah[mi], s + S2_AH + aRow + mi * 1024 + swa);
                ldsm4(al[mi], s + S2_AL + aRow + mi * 1024 + swa);
            }
#pragma unroll
            for (int np = 0; np < 2; np++) {
                const uint32_t bo = bRow + np * 1024 + swb;
                uint32_t bh[4], bl[4];
                ldsm4(bh, s + S2_BH + bo);
                ldsm4(bl, s + S2_BL + bo);
#pragma unroll
                for (int q = 0; q < 2; q++) {
                    const int ni = 2 * np + q;
#pragma unroll
                    for (int mi = 0; mi < 4; mi++) {
                        mma_bf16(acc[mi][ni], ah[mi], bh[q], bh[q + 2]);
                        mma_bf16(acc[mi][ni], al[mi], bh[q], bh[q + 2]);
                        mma_bf16(acc[mi][ni], ah[mi], bl[q], bl[q + 2]);
                    }
                }
            }
        }
    }

    // epilogue: gate-scale + atomic scatter (2 commutative adds onto 0)
    const int g = lane >> 2, tig = lane & 3;
#pragma unroll
    for (int mi = 0; mi < 4; mi++)
#pragma unroll
    for (int half = 0; half < 2; half++) {
        const int r = m0 + wm * 64 + mi * 16 + g + half * 8;
        if (r < cnt) {
            const int   tk   = g_tok[e * NTOK + r];
            const float gate = g_gate[e * NTOK + r];
            float* dst = out + (size_t)tk * HID + n0 + wn * 32 + tig * 2;
#pragma unroll
            for (int ni = 0; ni < 4; ni++) {
                atomicAdd(dst + ni * 8,     gate * acc[mi][ni][half * 2 + 0]);
                atomicAdd(dst + ni * 8 + 1, gate * acc[mi][ni][half * 2 + 1]);
            }
        }
    }
}

// ---------------------------------------------------------------------------
// Launch
// ---------------------------------------------------------------------------
extern "C" void kernel_launch(void* const* d_in, const int* in_sizes, int n_in,
                              void* d_out, int out_size) {
    const int*   mask = (const int*)d_in[0];
    const float* X    = (const float*)d_in[1];
    const float* rw   = (const float*)d_in[2];
    const float* w1   = (const float*)d_in[3];
    const float* w2   = (const float*)d_in[4];
    const float* w3   = (const float*)d_in[5];
    float* out = (float*)d_out;

    cudaFuncSetAttribute(gemm1_kernel, cudaFuncAttributeMaxDynamicSharedMemorySize, SMEM1);
    cudaFuncSetAttribute(gemm2_kernel, cudaFuncAttributeMaxDynamicSharedMemorySize, SMEM2);

    cudaMemsetAsync(out, 0, (size_t)out_size * sizeof(float));
    zero_counts_kernel<<<1, 32>>>();
    route_kernel<<<(NTOK * TOPK + 255) / 256, 256>>>(mask, rw);

    split_x_kernel<<<(NTOK * HID) / 512, 256>>>(X);
    dim3 tb(32, 8);
    transpose_split_kernel<0><<<dim3(INTER / 32, HID / 32, NEXP), tb>>>(w1, HID, INTER);
    transpose_split_kernel<1><<<dim3(INTER / 32, HID / 32, NEXP), tb>>>(w3, HID, INTER);
    transpose_split_kernel<2><<<dim3(HID / 32, INTER / 32, NEXP), tb>>>(w2, INTER, HID);

    gemm1_kernel<<<dim3(INTER / 128, NTOK / 128, NEXP), 256, SMEM1>>>();
    gemm2_kernel<<<dim3(HID / 128, NTOK / 128, NEXP), 256, SMEM2>>>(out);
}

// round 15
// speedup vs baseline: 1.1129x; 1.1129x over previous
#include <cuda_runtime.h>
#include <cuda_bf16.h>
#include <cstdint>

#define NEXP  8
#define TOPK  2
#define NTOK  4096
#define HID   1024
#define INTER 3584
#define KC    32

// ---------------------------------------------------------------------------
// Device scratch (zero-initialized globals)
// ---------------------------------------------------------------------------
__device__ int   g_count[NEXP];
__device__ int   g_tok[NEXP * NTOK];
__device__ float g_gate[NEXP * NTOK];

// pre-split operands (hi/lo bf16). Weights stored TRANSPOSED: [e][n][k], k-contig
__device__ __nv_bfloat16 g_xh[(size_t)NTOK * HID];
__device__ __nv_bfloat16 g_xl[(size_t)NTOK * HID];
__device__ __nv_bfloat16 g_w1h[(size_t)NEXP * INTER * HID];
__device__ __nv_bfloat16 g_w1l[(size_t)NEXP * INTER * HID];
__device__ __nv_bfloat16 g_w3h[(size_t)NEXP * INTER * HID];
__device__ __nv_bfloat16 g_w3l[(size_t)NEXP * INTER * HID];
__device__ __nv_bfloat16 g_w2h[(size_t)NEXP * HID * INTER];
__device__ __nv_bfloat16 g_w2l[(size_t)NEXP * HID * INTER];
// H intermediate, pre-split; rows >= cnt stay zero forever
__device__ __nv_bfloat16 g_hh[(size_t)NEXP * NTOK * INTER];
__device__ __nv_bfloat16 g_hl[(size_t)NEXP * NTOK * INTER];

// ---------------------------------------------------------------------------
// Helpers
// ---------------------------------------------------------------------------
__device__ __forceinline__ uint32_t smem_u32(const void* p) {
    uint32_t a;
    asm("{ .reg .u64 t; cvta.to.shared.u64 t, %1; cvt.u32.u64 %0, t; }"
        : "=r"(a) : "l"(p));
    return a;
}
__device__ __forceinline__ void cp16(uint32_t dst, const void* src) {
    asm volatile("cp.async.cg.shared.global [%0], [%1], 16;\n" :: "r"(dst), "l"(src));
}
__device__ __forceinline__ void cp_commit() {
    asm volatile("cp.async.commit_group;\n");
}
template <int N> __device__ __forceinline__ void cp_wait() {
    asm volatile("cp.async.wait_group %0;\n" :: "n"(N));
}
__device__ __forceinline__ void split2(float x, float y, uint32_t& h, uint32_t& l) {
    __nv_bfloat16 xh = __float2bfloat16(x);
    __nv_bfloat16 yh = __float2bfloat16(y);
    float xr = x - __bfloat162float(xh);
    float yr = y - __bfloat162float(yh);
    __nv_bfloat162 hh; hh.x = xh; hh.y = yh;
    __nv_bfloat162 ll = __floats2bfloat162_rn(xr, yr);
    h = *reinterpret_cast<uint32_t*>(&hh);
    l = *reinterpret_cast<uint32_t*>(&ll);
}
// b[2] comes from one ldsm2 -> contiguous registers, no SASS MOVs
__device__ __forceinline__ void mma_bf16(float d[4], const uint32_t a[4], const uint32_t b[2]) {
    asm volatile(
        "mma.sync.aligned.m16n8k16.row.col.f32.bf16.bf16.f32 "
        "{%0,%1,%2,%3}, {%4,%5,%6,%7}, {%8,%9}, {%0,%1,%2,%3};"
        : "+f"(d[0]), "+f"(d[1]), "+f"(d[2]), "+f"(d[3])
        : "r"(a[0]), "r"(a[1]), "r"(a[2]), "r"(a[3]), "r"(b[0]), "r"(b[1]));
}
__device__ __forceinline__ void ldsm4(uint32_t r[4], uint32_t addr) {
    asm volatile("ldmatrix.sync.aligned.m8n8.x4.shared.b16 {%0,%1,%2,%3}, [%4];"
                 : "=r"(r[0]), "=r"(r[1]), "=r"(r[2]), "=r"(r[3]) : "r"(addr));
}
__device__ __forceinline__ void ldsm2(uint32_t r[2], uint32_t addr) {
    asm volatile("ldmatrix.sync.aligned.m8n8.x2.shared.b16 {%0,%1}, [%2];"
                 : "=r"(r[0]), "=r"(r[1]) : "r"(addr));
}

// swizzled byte offset of 16B chunk c in 64B row r
#define SWC(r, c) ((((c) ^ (((r) >> 1) & 3))) * 16)

// ---------------------------------------------------------------------------
// Routing
// ---------------------------------------------------------------------------
__global__ void zero_counts_kernel() {
    if (threadIdx.x < NEXP) g_count[threadIdx.x] = 0;
}
__global__ void route_kernel(const int* __restrict__ mask,
                             const float* __restrict__ rw) {
    int idx = blockIdx.x * blockDim.x + threadIdx.x;
    if (idx >= NTOK * TOPK) return;
    int t = idx >> 1, k = idx & 1;
#pragma unroll
    for (int e = 0; e < NEXP; e++) {
        if (mask[(e * TOPK + k) * NTOK + t] != 0) {
            int slot = atomicAdd(&g_count[e], 1);
            g_tok[e * NTOK + slot]  = t;
            g_gate[e * NTOK + slot] = rw[t * TOPK + k];
            return;
        }
    }
}

// ---------------------------------------------------------------------------
// Pre-pass: split X (already k-contiguous)
// ---------------------------------------------------------------------------
__global__ void split_x_kernel(const float* __restrict__ x) {
    size_t i = ((size_t)blockIdx.x * blockDim.x + threadIdx.x) * 2;
    float2 v = *(const float2*)(x + i);
    uint32_t h, l;
    split2(v.x, v.y, h, l);
    *(uint32_t*)&g_xh[i] = h;
    *(uint32_t*)&g_xl[i] = l;
}

// ---------------------------------------------------------------------------
// Pre-pass: transpose + split weights. src [e][K][N] fp32 -> dst [e][N][K] bf16
// ---------------------------------------------------------------------------
template <int W>
__global__ void transpose_split_kernel(const float* __restrict__ src, int K, int N) {
    __shared__ float tile[32][33];
    const int e  = blockIdx.z;
    const int n0 = blockIdx.x * 32, k0 = blockIdx.y * 32;
    const int tx = threadIdx.x, ty = threadIdx.y;
    const float* s = src + ((size_t)e * K + k0) * N + n0;
#pragma unroll
    for (int j = 0; j < 4; j++)
        tile[ty + j * 8][tx] = s[(size_t)(ty + j * 8) * N + tx];
    __syncthreads();
    __nv_bfloat16* dh = (W == 0) ? g_w1h : (W == 1) ? g_w3h : g_w2h;
    __nv_bfloat16* dl = (W == 0) ? g_w1l : (W == 1) ? g_w3l : g_w2l;
    const int tid = ty * 32 + tx;
    const int kp  = tid & 15;
    const int nb  = tid >> 4;
#pragma unroll
    for (int it = 0; it < 2; it++) {
        int nl = nb + it * 16;
        uint32_t h, l;
        split2(tile[kp * 2][nl], tile[kp * 2 + 1][nl], h, l);
        size_t o = ((size_t)e * N + n0 + nl) * K + k0;
        ((uint32_t*)(dh + o))[kp] = h;
        ((uint32_t*)(dl + o))[kp] = l;
    }
}

// ---------------------------------------------------------------------------
// SMEM layouts: 64B rows, XOR-swizzled, 3-stage ring
// ---------------------------------------------------------------------------
#define S1_AH  0
#define S1_AL  8192
#define S1_B1H 16384
#define S1_B1L 24576
#define S1_B3H 32768
#define S1_B3L 40960
#define S1_STG 49152
#define SMEM1  (3 * S1_STG)    // 147456

#define S2_AH  0
#define S2_AL  8192
#define S2_BH  16384
#define S2_BL  24576
#define S2_STG 32768
#define SMEM2  (3 * S2_STG)    // 98304

// ---------------------------------------------------------------------------
// GEMM1: D1 = Xg@W1, D3 = Xg@W3, H = silu(D1)*D3 (split) -> g_hh/g_hl
// CTA 128x128, 8 warps (2m x 4n), warp 64x32 per matrix.
// 3-stage cp.async ring, ONE barrier per chunk, ldsm2 B fragments.
// ---------------------------------------------------------------------------
__global__ __launch_bounds__(256, 1)
void gemm1_kernel() {
    const int e   = blockIdx.z;
    const int cnt = g_count[e];
    const int m0  = blockIdx.y * 128;
    if (m0 >= cnt) return;
    const int n0  = blockIdx.x * 128;

    extern __shared__ char smem[];
    const uint32_t sb = smem_u32(smem);
    const int tid = threadIdx.x, lane = tid & 31, wid = tid >> 5;
    const int wm = wid & 1, wn = wid >> 1;

    const int srow = tid >> 1;
    const int sc0  = (tid & 1) * 2;
    int grow = m0 + srow; if (grow >= cnt) grow = cnt - 1;
    const size_t xoff = (size_t)g_tok[e * NTOK + grow] * HID + sc0 * 8;
    const size_t boff = ((size_t)(e * INTER + n0 + srow)) * HID + sc0 * 8;
    const uint32_t d0 = (uint32_t)(srow * 64 + SWC(srow, sc0));
    const uint32_t d1 = (uint32_t)(srow * 64 + SWC(srow, sc0 + 1));

    auto issue = [&](int c) {
        const uint32_t so = sb + (uint32_t)((c % 3) * S1_STG);
        const size_t ko = (size_t)c * KC;
        cp16(so + S1_AH  + d0, g_xh  + xoff + ko);
        cp16(so + S1_AH  + d1, g_xh  + xoff + ko + 8);
        cp16(so + S1_AL  + d0, g_xl  + xoff + ko);
        cp16(so + S1_AL  + d1, g_xl  + xoff + ko + 8);
        cp16(so + S1_B1H + d0, g_w1h + boff + ko);
        cp16(so + S1_B1H + d1, g_w1h + boff + ko + 8);
        cp16(so + S1_B1L + d0, g_w1l + boff + ko);
        cp16(so + S1_B1L + d1, g_w1l + boff + ko + 8);
        cp16(so + S1_B3H + d0, g_w3h + boff + ko);
        cp16(so + S1_B3H + d1, g_w3h + boff + ko + 8);
        cp16(so + S1_B3L + d0, g_w3l + boff + ko);
        cp16(so + S1_B3L + d1, g_w3l + boff + ko + 8);
        cp_commit();
    };

    const int rA = lane & 15, cA = lane >> 4, mA = (rA >> 1) & 3;
    const uint32_t aRow = (uint32_t)((wm * 64 + rA) * 64);
    const uint32_t swA0 = (uint32_t)(((cA) ^ mA) * 16);
    const uint32_t swA1 = (uint32_t)(((2 + cA) ^ mA) * 16);
    // B via ldsm2: lanes 0-7 -> (n rows 0-7, k0-7), lanes 8-15 -> (n rows 0-7, k8-15)
    const int rB = lane & 7, cB = (lane >> 3) & 1, mB = (rB >> 1) & 3;
    const uint32_t bRow = (uint32_t)((wn * 32 + rB) * 64);
    const uint32_t swB0 = (uint32_t)(((cB) ^ mB) * 16);
    const uint32_t swB1 = (uint32_t)(((2 + cB) ^ mB) * 16);

    float acc1[4][4][4] = {};
    float acc3[4][4][4] = {};

    issue(0);
    issue(1);
    const int NC = HID / KC;   // 32
    for (int c = 0; c < NC; c++) {
        cp_wait<1>();
        __syncthreads();           // all warps done reading chunk c-1
        if (c + 2 < NC) issue(c + 2);
        const uint32_t s = sb + (uint32_t)((c % 3) * S1_STG);
#pragma unroll
        for (int ks = 0; ks < 2; ks++) {
            const uint32_t swa = ks ? swA1 : swA0;
            const uint32_t swb = ks ? swB1 : swB0;
            uint32_t ah[4][4], al[4][4];
#pragma unroll
            for (int mi = 0; mi < 4; mi++) {
                ldsm4(ah[mi], s + S1_AH + aRow + mi * 1024 + swa);
                ldsm4(al[mi], s + S1_AL + aRow + mi * 1024 + swa);
            }
#pragma unroll
            for (int ni = 0; ni < 4; ni++) {      // 8 n-rows per ni
                const uint32_t bo = bRow + ni * 512 + swb;
                uint32_t bh[2], bl[2];
                ldsm2(bh, s + S1_B1H + bo);
                ldsm2(bl, s + S1_B1L + bo);
#pragma unroll
                for (int mi = 0; mi < 4; mi++) {
                    mma_bf16(acc1[mi][ni], ah[mi], bh);
                    mma_bf16(acc1[mi][ni], al[mi], bh);
                    mma_bf16(acc1[mi][ni], ah[mi], bl);
                }
                ldsm2(bh, s + S1_B3H + bo);
                ldsm2(bl, s + S1_B3L + bo);
#pragma unroll
                for (int mi = 0; mi < 4; mi++) {
                    mma_bf16(acc3[mi][ni], ah[mi], bh);
                    mma_bf16(acc3[mi][ni], al[mi], bh);
                    mma_bf16(acc3[mi][ni], ah[mi], bl);
                }
            }
        }
    }

    // epilogue: silu(D1)*D3, split, store
    const int g = lane >> 2, tig = lane & 3;
#pragma unroll
    for (int mi = 0; mi < 4; mi++)
#pragma unroll
    for (int half = 0; half < 2; half++) {
        const int r = m0 + wm * 64 + mi * 16 + g + half * 8;
        if (r < cnt) {
            const size_t base = ((size_t)e * NTOK + r) * INTER + n0 + wn * 32 + tig * 2;
#pragma unroll
            for (int ni = 0; ni < 4; ni++) {
                float x0 = acc1[mi][ni][half * 2 + 0];
                float x1 = acc1[mi][ni][half * 2 + 1];
                float h0 = (x0 / (1.f + __expf(-x0))) * acc3[mi][ni][half * 2 + 0];
                float h1 = (x1 / (1.f + __expf(-x1))) * acc3[mi][ni][half * 2 + 1];
                uint32_t hh, ll;
                split2(h0, h1, hh, ll);
                *(uint32_t*)&g_hh[base + ni * 8] = hh;
                *(uint32_t*)&g_hl[base + ni * 8] = ll;
            }
        }
    }
}

// ---------------------------------------------------------------------------
// GEMM2: out += gate * (H_e @ W2_e)
// ---------------------------------------------------------------------------
__global__ __launch_bounds__(256, 2)
void gemm2_kernel(float* __restrict__ out) {
    const int e   = blockIdx.z;
    const int cnt = g_count[e];
    const int m0  = blockIdx.y * 128;
    if (m0 >= cnt) return;
    const int n0  = blockIdx.x * 128;

    extern __shared__ char smem[];
    const uint32_t sb = smem_u32(smem);
    const int tid = threadIdx.x, lane = tid & 31, wid = tid >> 5;
    const int wm = wid & 1, wn = wid >> 1;

    const int srow = tid >> 1;
    const int sc0  = (tid & 1) * 2;
    const size_t aoff = ((size_t)e * NTOK + m0 + srow) * INTER + sc0 * 8;
    const size_t boff = ((size_t)(e * HID + n0 + srow)) * INTER + sc0 * 8;
    const uint32_t d0 = (uint32_t)(srow * 64 + SWC(srow, sc0));
    const uint32_t d1 = (uint32_t)(srow * 64 + SWC(srow, sc0 + 1));

    auto issue = [&](int c) {
        const uint32_t so = sb + (uint32_t)((c % 3) * S2_STG);
        const size_t ko = (size_t)c * KC;
        cp16(so + S2_AH + d0, g_hh  + aoff + ko);
        cp16(so + S2_AH + d1, g_hh  + aoff + ko + 8);
        cp16(so + S2_AL + d0, g_hl  + aoff + ko);
        cp16(so + S2_AL + d1, g_hl  + aoff + ko + 8);
        cp16(so + S2_BH + d0, g_w2h + boff + ko);
        cp16(so + S2_BH + d1, g_w2h + boff + ko + 8);
        cp16(so + S2_BL + d0, g_w2l + boff + ko);
        cp16(so + S2_BL + d1, g_w2l + boff + ko + 8);
        cp_commit();
    };

    const int rA = lane & 15, cA = lane >> 4, mA = (rA >> 1) & 3;
    const uint32_t aRow = (uint32_t)((wm * 64 + rA) * 64);
    const uint32_t swA0 = (uint32_t)(((cA) ^ mA) * 16);
    const uint32_t swA1 = (uint32_t)(((2 + cA) ^ mA) * 16);
    const int rB = lane & 7, cB = (lane >> 3) & 1, mB = (rB >> 1) & 3;
    const uint32_t bRow = (uint32_t)((wn * 32 + rB) * 64);
    const uint32_t swB0 = (uint32_t)(((cB) ^ mB) * 16);
    const uint32_t swB1 = (uint32_t)(((2 + cB) ^ mB) * 16);

    float acc[4][4][4] = {};

    issue(0);
    issue(1);
    const int NC = INTER / KC;   // 112
    for (int c = 0; c < NC; c++) {
        cp_wait<1>();
        __syncthreads();
        if (c + 2 < NC) issue(c + 2);
        const uint32_t s = sb + (uint32_t)((c % 3) * S2_STG);
#pragma unroll
        for (int ks = 0; ks < 2; ks++) {
            const uint32_t swa = ks ? swA1 : swA0;
            const uint32_t swb = ks ? swB1 : swB0;
            uint32_t ah[4][4], al[4][4];
#pragma unroll
            for (int mi = 0; mi < 4; mi++) {
                ldsm4(ah[mi], s + S2_AH + aRow + mi * 1024 + swa);
                ldsm4(al[mi], s + S2_AL + aRow + mi * 1024 + swa);
            }
#pragma unroll
            for (int ni = 0; ni < 4; ni++) {
                const uint32_t bo = bRow + ni * 512 + swb;
                uint32_t bh[2], bl[2];
                ldsm2(bh, s + S2_BH + bo);
                ldsm2(bl, s + S2_BL + bo);
#pragma unroll
                for (int mi = 0; mi < 4; mi++) {
                    mma_bf16(acc[mi][ni], ah[mi], bh);
                    mma_bf16(acc[mi][ni], al[mi], bh);
                    mma_bf16(acc[mi][ni], ah[mi], bl);
                }
            }
        }
    }

    // epilogue: gate-scale + atomic scatter (2 commutative adds onto 0)
    const int g = lane >> 2, tig = lane & 3;
#pragma unroll
    for (int mi = 0; mi < 4; mi++)
#pragma unroll
    for (int half = 0; half < 2; half++) {
        const int r = m0 + wm * 64 + mi * 16 + g + half * 8;
        if (r < cnt) {
            const int   tk   = g_tok[e * NTOK + r];
            const float gate = g_gate[e * NTOK + r];
            float* dst = out + (size_t)tk * HID + n0 + wn * 32 + tig * 2;
#pragma unroll
            for (int ni = 0; ni < 4; ni++) {
                atomicAdd(dst + ni * 8,     gate * acc[mi][ni][half * 2 + 0]);
                atomicAdd(dst + ni * 8 + 1, gate * acc[mi][ni][half * 2 + 1]);
            }
        }
    }
}

// ---------------------------------------------------------------------------
// Launch
// ---------------------------------------------------------------------------
extern "C" void kernel_launch(void* const* d_in, const int* in_sizes, int n_in,
                              void* d_out, int out_size) {
    const int*   mask = (const int*)d_in[0];
    const float* X    = (const float*)d_in[1];
    const float* rw   = (const float*)d_in[2];
    const float* w1   = (const float*)d_in[3];
    const float* w2   = (const float*)d_in[4];
    const float* w3   = (const float*)d_in[5];
    float* out = (float*)d_out;

    cudaFuncSetAttribute(gemm1_kernel, cudaFuncAttributeMaxDynamicSharedMemorySize, SMEM1);
    cudaFuncSetAttribute(gemm2_kernel, cudaFuncAttributeMaxDynamicSharedMemorySize, SMEM2);

    cudaMemsetAsync(out, 0, (size_t)out_size * sizeof(float));
    zero_counts_kernel<<<1, 32>>>();
    route_kernel<<<(NTOK * TOPK + 255) / 256, 256>>>(mask, rw);

    split_x_kernel<<<(NTOK * HID) / 512, 256>>>(X);
    dim3 tb(32, 8);
    transpose_split_kernel<0><<<dim3(INTER / 32, HID / 32, NEXP), tb>>>(w1, HID, INTER);
    transpose_split_kernel<1><<<dim3(INTER / 32, HID / 32, NEXP), tb>>>(w3, HID, INTER);
    transpose_split_kernel<2><<<dim3(HID / 32, INTER / 32, NEXP), tb>>>(w2, INTER, HID);

    gemm1_kernel<<<dim3(INTER / 128, NTOK / 128, NEXP), 256, SMEM1>>>();
    gemm2_kernel<<<dim3(HID / 128, NTOK / 128, NEXP), 256, SMEM2>>>(out);
}